// round 7
// baseline (speedup 1.0000x reference)
#include <cuda_runtime.h>
#include <cstddef>

#define Bsz 64
#define Lsz 2048
#define Dsz 256
#define TC 16
#define TP 32

// ---------------- scratch (static device globals; no runtime allocation) ----------------
__device__ float g_projkT[(size_t)Bsz * Dsz * Lsz];   // [b][d][l]
__device__ float g_W2[(size_t)Bsz * Dsz * Dsz];       // [b][k][e]
__device__ float g_sib[(size_t)TP * Bsz * Dsz];       // [t][b][d]
__device__ float g_gi[(size_t)TP * Bsz * 3 * Dsz];    // [t][b][o]
__device__ float g_q[(size_t)TP * Bsz * Dsz];         // [t][b][k]
__device__ float g_qq[(size_t)TP * Bsz * Dsz];        // [t][b][e]
__device__ float g_scores[(size_t)Bsz * TP * Lsz];    // [b][t][l]
__device__ float g_WhhT[Dsz * 3 * Dsz];               // [d][o]

typedef unsigned long long ull;

__device__ __forceinline__ float fast_tanh_exact(float x) {
    float e = __expf(2.f * x);
    return 1.f - __fdividef(2.f, e + 1.f);
}
__device__ __forceinline__ float fast_sigmoid(float x) {
    return __fdividef(1.f, 1.f + __expf(-x));
}
__device__ __forceinline__ float tanha(float x) {
    float y;
    asm("tanh.approx.f32 %0, %1;" : "=f"(y) : "f"(x));
    return y;
}
__device__ __forceinline__ ull dup2(float x) {
    ull r;
    asm("mov.b64 %0, {%1, %1};" : "=l"(r) : "f"(x));
    return r;
}
__device__ __forceinline__ void unpack2(ull v, float& lo, float& hi) {
    asm("mov.b64 {%0, %1}, %2;" : "=f"(lo), "=f"(hi) : "l"(v));
}
__device__ __forceinline__ void ffma2(ull& d, ull a, ull b) {
    asm("fma.rn.f32x2 %0, %1, %2, %0;" : "+l"(d) : "l"(a), "l"(b));
}

// ---------------- FFMA2 GEMM: C[M,N] = gather(A)[M,K] @ B (+bias) ----------------
// 128x128 tile, BK=16, 256 threads, 8x8 micro-tile with m-paired f32x2 accumulators.
// BTRANS: B stored [n][k] (ld=K) else [k][n] (ld=N)
// CTRANS: write C[bz][n][m] (projkT); else C[m*ldc+n]
// GATHER: A row m -> A[(b*Lrow + gold[b*Tg+t])*lda], m = t*64 + b
#define BM 128
#define BN 128
#define BK 16

template<int BTRANS, int CTRANS, int GATHER, int HASBIAS>
__global__ __launch_bounds__(256, 2)
void tgemm_kernel(const float* __restrict__ A, int lda,
                  const float* __restrict__ Bm,
                  const float* __restrict__ bias,
                  float* __restrict__ C, int ldc,
                  int M, int N, int K,
                  const int* __restrict__ gold, int Tg, int Lrow)
{
    __shared__ float As[BK][BM];
    __shared__ float Bs[BK][BN];
    const int tid = threadIdx.x;
    const int m0 = blockIdx.x * BM;
    const int n0 = blockIdx.y * BN;
    const int bz = blockIdx.z;

    const float* Ab = A;
    if (!GATHER) Ab = A + (size_t)bz * M * lda;

    const int ty = tid & 15;   // m dir (fast -> coalesced transposed stores)
    const int tx = tid >> 4;   // n dir

    ull acc2[4][8];
#pragma unroll
    for (int i = 0; i < 4; i++)
#pragma unroll
        for (int j = 0; j < 8; j++) acc2[i][j] = 0ull;

    for (int k0 = 0; k0 < K; k0 += BK) {
        // A tile: 128 rows x 16 k  (512 float4 / 256 threads)
#pragma unroll
        for (int rep = 0; rep < 2; rep++) {
            int idx = tid + rep * 256;
            int row = idx >> 2;
            int c4 = idx & 3;
            int gm = m0 + row;
            const float* src;
            if (GATHER) {
                int t = gm >> 6;
                int b = gm & 63;
                int l = gold[b * Tg + t];
                src = A + ((size_t)b * Lrow + l) * lda + k0 + c4 * 4;
            } else {
                src = Ab + (size_t)gm * lda + k0 + c4 * 4;
            }
            float4 v = *reinterpret_cast<const float4*>(src);
            As[c4 * 4 + 0][row] = v.x;
            As[c4 * 4 + 1][row] = v.y;
            As[c4 * 4 + 2][row] = v.z;
            As[c4 * 4 + 3][row] = v.w;
        }
        // B tile: 16 k x 128 n
        if (!BTRANS) {
#pragma unroll
            for (int rep = 0; rep < 2; rep++) {
                int idx = tid + rep * 256;
                int k = idx >> 5;
                int n4 = idx & 31;
                float4 v = *reinterpret_cast<const float4*>(&Bm[(size_t)(k0 + k) * N + n0 + n4 * 4]);
                *reinterpret_cast<float4*>(&Bs[k][n4 * 4]) = v;
            }
        } else {
#pragma unroll
            for (int rep = 0; rep < 2; rep++) {
                int idx = tid + rep * 256;
                int n = idx >> 2;
                int kq = idx & 3;
                float4 v = *reinterpret_cast<const float4*>(&Bm[(size_t)(n0 + n) * K + k0 + kq * 4]);
                Bs[kq * 4 + 0][n] = v.x;
                Bs[kq * 4 + 1][n] = v.y;
                Bs[kq * 4 + 2][n] = v.z;
                Bs[kq * 4 + 3][n] = v.w;
            }
        }
        __syncthreads();
#pragma unroll
        for (int kk = 0; kk < BK; kk++) {
            ulonglong2 av0 = *reinterpret_cast<const ulonglong2*>(&As[kk][ty * 8]);
            ulonglong2 av1 = *reinterpret_cast<const ulonglong2*>(&As[kk][ty * 8 + 4]);
            ull a2[4] = { av0.x, av0.y, av1.x, av1.y };
            float4 bv0 = *reinterpret_cast<const float4*>(&Bs[kk][tx * 8]);
            float4 bv1 = *reinterpret_cast<const float4*>(&Bs[kk][tx * 8 + 4]);
            ull b2[8] = { dup2(bv0.x), dup2(bv0.y), dup2(bv0.z), dup2(bv0.w),
                          dup2(bv1.x), dup2(bv1.y), dup2(bv1.z), dup2(bv1.w) };
#pragma unroll
            for (int j = 0; j < 8; j++)
#pragma unroll
                for (int i = 0; i < 4; i++)
                    ffma2(acc2[i][j], a2[i], b2[j]);
        }
        __syncthreads();
    }

    if (CTRANS) {
        float* Cb = C + (size_t)bz * N * ldc;
#pragma unroll
        for (int j = 0; j < 8; j++) {
            int n = n0 + tx * 8 + j;
            float v[8];
#pragma unroll
            for (int i = 0; i < 4; i++) unpack2(acc2[i][j], v[2 * i], v[2 * i + 1]);
            size_t base = (size_t)n * ldc + m0 + ty * 8;
            *reinterpret_cast<float4*>(&Cb[base]) = make_float4(v[0], v[1], v[2], v[3]);
            *reinterpret_cast<float4*>(&Cb[base + 4]) = make_float4(v[4], v[5], v[6], v[7]);
        }
    } else {
        float bb[8];
#pragma unroll
        for (int j = 0; j < 8; j++) bb[j] = HASBIAS ? bias[n0 + tx * 8 + j] : 0.f;
#pragma unroll
        for (int i = 0; i < 4; i++) {
            float lo[8], hi[8];
#pragma unroll
            for (int j = 0; j < 8; j++) {
                unpack2(acc2[i][j], lo[j], hi[j]);
                lo[j] += bb[j];
                hi[j] += bb[j];
            }
            size_t r0 = (size_t)(m0 + ty * 8 + 2 * i) * ldc + n0 + tx * 8;
            size_t r1 = r0 + ldc;
            *reinterpret_cast<float4*>(&C[r0]) = make_float4(lo[0], lo[1], lo[2], lo[3]);
            *reinterpret_cast<float4*>(&C[r0 + 4]) = make_float4(lo[4], lo[5], lo[6], lo[7]);
            *reinterpret_cast<float4*>(&C[r1]) = make_float4(hi[0], hi[1], hi[2], hi[3]);
            *reinterpret_cast<float4*>(&C[r1 + 4]) = make_float4(hi[4], hi[5], hi[6], hi[7]);
        }
    }
}

// ---------------- Whh transpose: WhhT[d][o] = Whh[o][d] ----------------
__global__ void transpose_whh(const float* __restrict__ Whh, float* __restrict__ WhhT)
{
    int idx = blockIdx.x * 256 + threadIdx.x;
    int o = idx >> 8;
    int d = idx & 255;
    WhhT[d * 768 + o] = Whh[idx];
}

// ---------------- W2[b][k][e] = sum_d parent[b][d] * bilW[k][d][e] ----------------
// grid 256 (k), 256 threads (e). FFMA2 over b-pairs, broadcast smem loads, w prefetch.
__global__ __launch_bounds__(256, 2)
void w2_kernel(const float* __restrict__ bilW, const float* __restrict__ feat,
               float* __restrict__ W2)
{
    __shared__ float par[128][64];  // [d_local][b]
    const int k = blockIdx.x;
    const int e = threadIdx.x;
    ull acc2[32];
#pragma unroll
    for (int p = 0; p < 32; p++) acc2[p] = 0ull;

    for (int half = 0; half < 2; half++) {
        __syncthreads();
        for (int i = threadIdx.x; i < 128 * 64; i += 256) {
            int d = i >> 6;
            int b = i & 63;
            par[d][b] = feat[((size_t)b * Lsz + (Lsz - 2)) * Dsz + half * 128 + d];
        }
        __syncthreads();
        const float* wp = bilW + (size_t)k * Dsz * Dsz + (size_t)half * 128 * Dsz + e;
        float wreg[4];
#pragma unroll
        for (int u = 0; u < 4; u++) wreg[u] = wp[(size_t)u * Dsz];
        for (int d0 = 0; d0 < 128; d0 += 4) {
            float wnext[4];
#pragma unroll
            for (int u = 0; u < 4; u++) {
                int dn = d0 + 4 + u;
                if (dn > 127) dn = 127;
                wnext[u] = wp[(size_t)dn * Dsz];
            }
#pragma unroll
            for (int u = 0; u < 4; u++) {
                ull wd = dup2(wreg[u]);
                const ulonglong2* pp = reinterpret_cast<const ulonglong2*>(par[d0 + u]);
#pragma unroll
                for (int bi = 0; bi < 16; bi++) {
                    ulonglong2 pv = pp[bi];
                    ffma2(acc2[2 * bi + 0], pv.x, wd);
                    ffma2(acc2[2 * bi + 1], pv.y, wd);
                }
            }
#pragma unroll
            for (int u = 0; u < 4; u++) wreg[u] = wnext[u];
        }
    }
#pragma unroll
    for (int p = 0; p < 32; p++) {
        float lo, hi;
        unpack2(acc2[p], lo, hi);
        W2[((size_t)(2 * p + 0) * Dsz + k) * Dsz + e] = lo;
        W2[((size_t)(2 * p + 1) * Dsz + k) * Dsz + e] = hi;
    }
}

// ---------------- GRU chain: 2 batches per block, FFMA2 over batch pairs ----------------
__global__ void gru_kernel(const float* __restrict__ gi, const float* __restrict__ WhhT,
                           const float* __restrict__ bhh, const float* __restrict__ query,
                           float* __restrict__ sib, int T)
{
    __shared__ float hT[256][2];   // [d][batch]
    __shared__ float ghs[768][2];  // [o][batch]
    const int bb0 = blockIdx.x * 2;
    const int o = threadIdx.x;   // 0..767

    if (o < 256) {
        float qv = query[o];
        hT[o][0] = qv;
        hT[o][1] = qv;
        sib[((size_t)0 * Bsz + bb0 + 0) * Dsz + o] = qv;
        sib[((size_t)0 * Bsz + bb0 + 1) * Dsz + o] = qv;
    }
    __syncthreads();
    const float bo = bhh[o];

    for (int t = 0; t < T - 1; t++) {
        ull acc = 0ull;
        const float* wcol = WhhT + o;
#pragma unroll 8
        for (int d = 0; d < 256; d++) {
            float w = wcol[d * 768];
            ull h2 = *reinterpret_cast<const ull*>(&hT[d][0]);
            ffma2(acc, h2, dup2(w));
        }
        float g0, g1;
        unpack2(acc, g0, g1);
        ghs[o][0] = g0 + bo;
        ghs[o][1] = g1 + bo;
        __syncthreads();
        if (o < 256) {
#pragma unroll
            for (int j = 0; j < 2; j++) {
                const float* gib = gi + ((size_t)t * Bsz + bb0 + j) * 768;
                float r = fast_sigmoid(gib[o] + ghs[o][j]);
                float z = fast_sigmoid(gib[256 + o] + ghs[256 + o][j]);
                float n = fast_tanh_exact(gib[512 + o] + r * ghs[512 + o][j]);
                float hn = (1.f - z) * n + z * hT[o][j];
                hT[o][j] = hn;
                sib[((size_t)(t + 1) * Bsz + bb0 + j) * Dsz + o] = hn;
            }
        }
        __syncthreads();
    }
}

// ---------------- q[t][b][k] = sum_e W2[b][k][e]*sib[t][b][e] + bil_b[k] ----------------
template<int T>
__global__ void q_kernel(const float* __restrict__ W2, const float* __restrict__ sib,
                         const float* __restrict__ bil_b, float* __restrict__ q)
{
    __shared__ float ssib[T][256];
    const int b = blockIdx.x;
    for (int i = threadIdx.x; i < T * 256; i += 256) {
        int t = i >> 8;
        int e = i & 255;
        ssib[t][e] = sib[((size_t)t * Bsz + b) * Dsz + e];
    }
    __syncthreads();
    const int k = threadIdx.x;
    float acc[T];
#pragma unroll
    for (int t = 0; t < T; t++) acc[t] = 0.f;
    const float* wrow = W2 + ((size_t)b * Dsz + k) * Dsz;
#pragma unroll 1
    for (int e0 = 0; e0 < 256; e0 += 8) {
        float4 w0 = *reinterpret_cast<const float4*>(wrow + e0);
        float4 w1 = *reinterpret_cast<const float4*>(wrow + e0 + 4);
#pragma unroll
        for (int t = 0; t < T; t++) {
            const float4* sb = reinterpret_cast<const float4*>(&ssib[t][e0]);
            float4 s0 = sb[0], s1 = sb[1];
            acc[t] += w0.x * s0.x + w0.y * s0.y + w0.z * s0.z + w0.w * s0.w
                    + w1.x * s1.x + w1.y * s1.y + w1.z * s1.z + w1.w * s1.w;
        }
    }
    float bb = bil_b[k];
#pragma unroll
    for (int t = 0; t < T; t++)
        q[((size_t)t * Bsz + b) * Dsz + k] = acc[t] + bb;
}

// ---------------- scores[b][t][l] = sum_d v[d]*tanh(projkT[b][d][l] + qq[t][b][d]) -----
template<int T>
__global__ void score_kernel(const float* __restrict__ projkT, const float* __restrict__ qq,
                             const float* __restrict__ attn_v, float* __restrict__ scores)
{
    __shared__ float sqq[T][256];
    __shared__ float sv[256];
    const int b = blockIdx.y;
    const int l = blockIdx.x * 256 + threadIdx.x;
    for (int i = threadIdx.x; i < T * 256; i += 256) {
        int t = i >> 8;
        int d = i & 255;
        sqq[t][d] = qq[((size_t)t * Bsz + b) * Dsz + d];
    }
    sv[threadIdx.x] = attn_v[threadIdx.x];
    __syncthreads();

    float acc[T];
#pragma unroll
    for (int t = 0; t < T; t++) acc[t] = 0.f;
    const float* pk = projkT + (size_t)b * Dsz * Lsz + l;
#pragma unroll 2
    for (int d = 0; d < 256; d++) {
        float p = pk[(size_t)d * Lsz];
        float v = sv[d];
#pragma unroll
        for (int t = 0; t < T; t++)
            acc[t] += v * tanha(p + sqq[t][d]);
    }
#pragma unroll
    for (int t = 0; t < T; t++)
        scores[((size_t)b * T + t) * Lsz + l] = acc[t];
}

// ---------------- softmax-at-gold: out[b][t] = softmax(scores[b][t])[gold[b][t]] -------
__global__ void prob_kernel(const float* __restrict__ scores, const int* __restrict__ mask,
                            const int* __restrict__ gold, int T, float* __restrict__ out)
{
    __shared__ float red[256];
    const int bt = blockIdx.x;
    const int b = bt / T;
    const int t = bt - b * T;
    const float* s = scores + (size_t)bt * Lsz;
    const int* mk = mask + (size_t)b * Lsz;

    float vals[8];
    float mx = -3.0e38f;
#pragma unroll
    for (int j = 0; j < 8; j++) {
        int l = threadIdx.x + j * 256;
        float v = (mk[l] != 0) ? s[l] : -1e9f;
        vals[j] = v;
        mx = fmaxf(mx, v);
    }
    red[threadIdx.x] = mx;
    __syncthreads();
    for (int st = 128; st > 0; st >>= 1) {
        if (threadIdx.x < st) red[threadIdx.x] = fmaxf(red[threadIdx.x], red[threadIdx.x + st]);
        __syncthreads();
    }
    float M = red[0];
    __syncthreads();
    float sm = 0.f;
#pragma unroll
    for (int j = 0; j < 8; j++) sm += __expf(vals[j] - M);
    red[threadIdx.x] = sm;
    __syncthreads();
    for (int st = 128; st > 0; st >>= 1) {
        if (threadIdx.x < st) red[threadIdx.x] += red[threadIdx.x + st];
        __syncthreads();
    }
    if (threadIdx.x == 0) {
        int g = gold[b * T + t];
        float sg = (mk[g] != 0) ? s[g] : -1e9f;
        out[b * T + t] = __expf(sg - M) / red[0];
    }
}

// ---------------- host orchestration ----------------
static void run_network(const float* feat, const float* query, const int* gold, const int* mask,
                        const float* bilW, const float* bil_b, const float* Wq, const float* Wk,
                        const float* attn_b, const float* attn_v, const float* Wih,
                        const float* Whh, const float* bih, const float* bhh,
                        int T, float* out,
                        float* s_projkT, float* s_W2, float* s_sib, float* s_gi,
                        float* s_q, float* s_qq, float* s_scores, float* s_WhhT)
{
    const int M = T * Bsz;
    transpose_whh<<<768, 256>>>(Whh, s_WhhT);
    // gi = gather(feat, gold) @ Wih^T + bih   (M x 768)
    tgemm_kernel<1, 0, 1, 1><<<dim3(M / BM, 768 / BN), 256>>>(
        feat, Dsz, Wih, bih, s_gi, 768, M, 768, Dsz, gold, T, Lsz);
    gru_kernel<<<32, 768>>>(s_gi, s_WhhT, bhh, query, s_sib, T);
    w2_kernel<<<256, 256>>>(bilW, feat, s_W2);
    if (T == TC) q_kernel<TC><<<Bsz, 256>>>(s_W2, s_sib, bil_b, s_q);
    else         q_kernel<TP><<<Bsz, 256>>>(s_W2, s_sib, bil_b, s_q);
    // qq = q @ Wq + attn_b   (M x 256)
    tgemm_kernel<0, 0, 0, 1><<<dim3(M / BM, Dsz / BN), 256>>>(
        s_q, Dsz, Wq, attn_b, s_qq, Dsz, M, Dsz, Dsz, nullptr, 0, 0);
    // projkT[b][d][l] = (emb_b @ Wk)^T   per-b via grid.z
    tgemm_kernel<0, 1, 0, 0><<<dim3(Lsz / BM, Dsz / BN, Bsz), 256>>>(
        feat, Dsz, Wk, nullptr, s_projkT, Lsz, Lsz, Dsz, Dsz, nullptr, 0, 0);
    if (T == TC) score_kernel<TC><<<dim3(Lsz / 256, Bsz), 256>>>(s_projkT, s_qq, attn_v, s_scores);
    else         score_kernel<TP><<<dim3(Lsz / 256, Bsz), 256>>>(s_projkT, s_qq, attn_v, s_scores);
    prob_kernel<<<Bsz * T, 256>>>(s_scores, mask, gold, T, out);
}

extern "C" void kernel_launch(void* const* d_in, const int* in_sizes, int n_in,
                              void* d_out, int out_size)
{
    (void)n_in; (void)out_size;
    int iFeat, iMask, iGC, iGP, iQC, iQP, c0, p0;
    if (in_sizes[1] == Bsz * Lsz) {
        iFeat = 0; iMask = 1; iGC = 2; iGP = 3; iQC = 4; iQP = 5; c0 = 6; p0 = 16;
    } else {
        iFeat = 0; iQC = 1; iQP = 2; c0 = 3; p0 = 13; iMask = 23; iGC = 24; iGP = 25;
    }
    const float* feat = (const float*)d_in[iFeat];
    const int* mask = (const int*)d_in[iMask];
    const int* gold_c = (const int*)d_in[iGC];
    const int* gold_p = (const int*)d_in[iGP];
    const float* q_c = (const float*)d_in[iQC];
    const float* q_p = (const float*)d_in[iQP];
    float* out = (float*)d_out;

    float *s_projkT, *s_W2, *s_sib, *s_gi, *s_q, *s_qq, *s_scores, *s_WhhT;
    cudaGetSymbolAddress((void**)&s_projkT, g_projkT);
    cudaGetSymbolAddress((void**)&s_W2, g_W2);
    cudaGetSymbolAddress((void**)&s_sib, g_sib);
    cudaGetSymbolAddress((void**)&s_gi, g_gi);
    cudaGetSymbolAddress((void**)&s_q, g_q);
    cudaGetSymbolAddress((void**)&s_qq, g_qq);
    cudaGetSymbolAddress((void**)&s_scores, g_scores);
    cudaGetSymbolAddress((void**)&s_WhhT, g_WhhT);

    run_network(feat, q_c, gold_c, mask,
                (const float*)d_in[c0 + 0], (const float*)d_in[c0 + 1],
                (const float*)d_in[c0 + 2], (const float*)d_in[c0 + 3],
                (const float*)d_in[c0 + 4], (const float*)d_in[c0 + 5],
                (const float*)d_in[c0 + 6], (const float*)d_in[c0 + 7],
                (const float*)d_in[c0 + 8], (const float*)d_in[c0 + 9],
                TC, out,
                s_projkT, s_W2, s_sib, s_gi, s_q, s_qq, s_scores, s_WhhT);

    run_network(feat, q_p, gold_p, mask,
                (const float*)d_in[p0 + 0], (const float*)d_in[p0 + 1],
                (const float*)d_in[p0 + 2], (const float*)d_in[p0 + 3],
                (const float*)d_in[p0 + 4], (const float*)d_in[p0 + 5],
                (const float*)d_in[p0 + 6], (const float*)d_in[p0 + 7],
                (const float*)d_in[p0 + 8], (const float*)d_in[p0 + 9],
                TP, out + Bsz * TC,
                s_projkT, s_W2, s_sib, s_gi, s_q, s_qq, s_scores, s_WhhT);
}

// round 8
// speedup vs baseline: 1.0035x; 1.0035x over previous
#include <cuda_runtime.h>
#include <cstddef>

#define Bsz 64
#define Lsz 2048
#define Dsz 256
#define TC 16
#define TP 32

// ---------------- scratch (static device globals; no runtime allocation) ----------------
__device__ float g_projkT[(size_t)Bsz * Dsz * Lsz];   // [b][d][l]
__device__ float g_W2[(size_t)Bsz * Dsz * Dsz];       // [b][k][e]
__device__ float g_sib[(size_t)TP * Bsz * Dsz];       // [t][b][d]
__device__ float g_gi[(size_t)TP * Bsz * 3 * Dsz];    // [t][b][o]
__device__ float g_q[(size_t)TP * Bsz * Dsz];         // [t][b][k]
__device__ float g_qq[(size_t)TP * Bsz * Dsz];        // [t][b][e]
__device__ float g_scores[(size_t)Bsz * TP * Lsz];    // [b][t][l]
__device__ float g_WhhT[Dsz * 3 * Dsz];               // [d][o]

typedef unsigned long long ull;

__device__ __forceinline__ float fast_tanh_exact(float x) {
    float e = __expf(2.f * x);
    return 1.f - __fdividef(2.f, e + 1.f);
}
__device__ __forceinline__ float fast_sigmoid(float x) {
    return __fdividef(1.f, 1.f + __expf(-x));
}
__device__ __forceinline__ float tanha(float x) {
    float y;
    asm("tanh.approx.f32 %0, %1;" : "=f"(y) : "f"(x));
    return y;
}
__device__ __forceinline__ ull dup2(float x) {
    ull r;
    asm("mov.b64 %0, {%1, %1};" : "=l"(r) : "f"(x));
    return r;
}
__device__ __forceinline__ void unpack2(ull v, float& lo, float& hi) {
    asm("mov.b64 {%0, %1}, %2;" : "=f"(lo), "=f"(hi) : "l"(v));
}
__device__ __forceinline__ void ffma2(ull& d, ull a, ull b) {
    asm("fma.rn.f32x2 %0, %1, %2, %0;" : "+l"(d) : "l"(a), "l"(b));
}

// ---------------- FFMA2 GEMM: C[M,N] = gather(A)[M,K] @ B (+bias) ----------------
// 128x128 tile, BK=16, 256 threads, 8x8 micro-tile with m-paired f32x2 accumulators.
// BTRANS: B stored [n][k] (ld=K) else [k][n] (ld=N)
// CTRANS: write C[bz][n][m] (projkT); else C[m*ldc+n]
// GATHER: A row m -> A[(b*Lrow + gold[b*Tg+t])*lda], m = t*64 + b
#define BM 128
#define BN 128
#define BK 16

template<int BTRANS, int CTRANS, int GATHER, int HASBIAS>
__global__ __launch_bounds__(256, 2)
void tgemm_kernel(const float* __restrict__ A, int lda,
                  const float* __restrict__ Bm,
                  const float* __restrict__ bias,
                  float* __restrict__ C, int ldc,
                  int M, int N, int K,
                  const int* __restrict__ gold, int Tg, int Lrow)
{
    __shared__ float As[BK][BM];
    __shared__ float Bs[BK][BN];
    const int tid = threadIdx.x;
    const int m0 = blockIdx.x * BM;
    const int n0 = blockIdx.y * BN;
    const int bz = blockIdx.z;

    const float* Ab = A;
    if (!GATHER) Ab = A + (size_t)bz * M * lda;

    const int ty = tid & 15;   // m dir (fast -> coalesced transposed stores)
    const int tx = tid >> 4;   // n dir

    ull acc2[4][8];
#pragma unroll
    for (int i = 0; i < 4; i++)
#pragma unroll
        for (int j = 0; j < 8; j++) acc2[i][j] = 0ull;

    for (int k0 = 0; k0 < K; k0 += BK) {
        // A tile: 128 rows x 16 k  (512 float4 / 256 threads)
#pragma unroll
        for (int rep = 0; rep < 2; rep++) {
            int idx = tid + rep * 256;
            int row = idx >> 2;
            int c4 = idx & 3;
            int gm = m0 + row;
            const float* src;
            if (GATHER) {
                int t = gm >> 6;
                int b = gm & 63;
                int l = gold[b * Tg + t];
                src = A + ((size_t)b * Lrow + l) * lda + k0 + c4 * 4;
            } else {
                src = Ab + (size_t)gm * lda + k0 + c4 * 4;
            }
            float4 v = *reinterpret_cast<const float4*>(src);
            As[c4 * 4 + 0][row] = v.x;
            As[c4 * 4 + 1][row] = v.y;
            As[c4 * 4 + 2][row] = v.z;
            As[c4 * 4 + 3][row] = v.w;
        }
        // B tile: 16 k x 128 n
        if (!BTRANS) {
#pragma unroll
            for (int rep = 0; rep < 2; rep++) {
                int idx = tid + rep * 256;
                int k = idx >> 5;
                int n4 = idx & 31;
                float4 v = *reinterpret_cast<const float4*>(&Bm[(size_t)(k0 + k) * N + n0 + n4 * 4]);
                *reinterpret_cast<float4*>(&Bs[k][n4 * 4]) = v;
            }
        } else {
#pragma unroll
            for (int rep = 0; rep < 2; rep++) {
                int idx = tid + rep * 256;
                int n = idx >> 2;
                int kq = idx & 3;
                float4 v = *reinterpret_cast<const float4*>(&Bm[(size_t)(n0 + n) * K + k0 + kq * 4]);
                Bs[kq * 4 + 0][n] = v.x;
                Bs[kq * 4 + 1][n] = v.y;
                Bs[kq * 4 + 2][n] = v.z;
                Bs[kq * 4 + 3][n] = v.w;
            }
        }
        __syncthreads();
#pragma unroll
        for (int kk = 0; kk < BK; kk++) {
            ulonglong2 av0 = *reinterpret_cast<const ulonglong2*>(&As[kk][ty * 8]);
            ulonglong2 av1 = *reinterpret_cast<const ulonglong2*>(&As[kk][ty * 8 + 4]);
            ull a2[4] = { av0.x, av0.y, av1.x, av1.y };
            float4 bv0 = *reinterpret_cast<const float4*>(&Bs[kk][tx * 8]);
            float4 bv1 = *reinterpret_cast<const float4*>(&Bs[kk][tx * 8 + 4]);
            ull b2[8] = { dup2(bv0.x), dup2(bv0.y), dup2(bv0.z), dup2(bv0.w),
                          dup2(bv1.x), dup2(bv1.y), dup2(bv1.z), dup2(bv1.w) };
#pragma unroll
            for (int j = 0; j < 8; j++)
#pragma unroll
                for (int i = 0; i < 4; i++)
                    ffma2(acc2[i][j], a2[i], b2[j]);
        }
        __syncthreads();
    }

    if (CTRANS) {
        float* Cb = C + (size_t)bz * N * ldc;
#pragma unroll
        for (int j = 0; j < 8; j++) {
            int n = n0 + tx * 8 + j;
            float v[8];
#pragma unroll
            for (int i = 0; i < 4; i++) unpack2(acc2[i][j], v[2 * i], v[2 * i + 1]);
            size_t base = (size_t)n * ldc + m0 + ty * 8;
            *reinterpret_cast<float4*>(&Cb[base]) = make_float4(v[0], v[1], v[2], v[3]);
            *reinterpret_cast<float4*>(&Cb[base + 4]) = make_float4(v[4], v[5], v[6], v[7]);
        }
    } else {
        float bb[8];
#pragma unroll
        for (int j = 0; j < 8; j++) bb[j] = HASBIAS ? bias[n0 + tx * 8 + j] : 0.f;
#pragma unroll
        for (int i = 0; i < 4; i++) {
            float lo[8], hi[8];
#pragma unroll
            for (int j = 0; j < 8; j++) {
                unpack2(acc2[i][j], lo[j], hi[j]);
                lo[j] += bb[j];
                hi[j] += bb[j];
            }
            size_t r0 = (size_t)(m0 + ty * 8 + 2 * i) * ldc + n0 + tx * 8;
            size_t r1 = r0 + ldc;
            *reinterpret_cast<float4*>(&C[r0]) = make_float4(lo[0], lo[1], lo[2], lo[3]);
            *reinterpret_cast<float4*>(&C[r0 + 4]) = make_float4(lo[4], lo[5], lo[6], lo[7]);
            *reinterpret_cast<float4*>(&C[r1]) = make_float4(hi[0], hi[1], hi[2], hi[3]);
            *reinterpret_cast<float4*>(&C[r1 + 4]) = make_float4(hi[4], hi[5], hi[6], hi[7]);
        }
    }
}

// ---------------- Whh transpose: WhhT[d][o] = Whh[o][d] ----------------
__global__ void transpose_whh(const float* __restrict__ Whh, float* __restrict__ WhhT)
{
    int idx = blockIdx.x * 256 + threadIdx.x;
    int o = idx >> 8;
    int d = idx & 255;
    WhhT[d * 768 + o] = Whh[idx];
}

// ---------------- W2[b][k][e] = sum_d parent[b][d] * bilW[k][d][e] ----------------
// grid 256 (k), 256 threads (e). FFMA2 over b-pairs, broadcast smem loads, w prefetch.
__global__ __launch_bounds__(256, 2)
void w2_kernel(const float* __restrict__ bilW, const float* __restrict__ feat,
               float* __restrict__ W2)
{
    __shared__ float par[128][64];  // [d_local][b]
    const int k = blockIdx.x;
    const int e = threadIdx.x;
    ull acc2[32];
#pragma unroll
    for (int p = 0; p < 32; p++) acc2[p] = 0ull;

    for (int half = 0; half < 2; half++) {
        __syncthreads();
        for (int i = threadIdx.x; i < 128 * 64; i += 256) {
            int d = i >> 6;
            int b = i & 63;
            par[d][b] = feat[((size_t)b * Lsz + (Lsz - 2)) * Dsz + half * 128 + d];
        }
        __syncthreads();
        const float* wp = bilW + (size_t)k * Dsz * Dsz + (size_t)half * 128 * Dsz + e;
        float wreg[4];
#pragma unroll
        for (int u = 0; u < 4; u++) wreg[u] = wp[(size_t)u * Dsz];
        for (int d0 = 0; d0 < 128; d0 += 4) {
            float wnext[4];
#pragma unroll
            for (int u = 0; u < 4; u++) {
                int dn = d0 + 4 + u;
                if (dn > 127) dn = 127;
                wnext[u] = wp[(size_t)dn * Dsz];
            }
#pragma unroll
            for (int u = 0; u < 4; u++) {
                ull wd = dup2(wreg[u]);
                const ulonglong2* pp = reinterpret_cast<const ulonglong2*>(par[d0 + u]);
#pragma unroll
                for (int bi = 0; bi < 16; bi++) {
                    ulonglong2 pv = pp[bi];
                    ffma2(acc2[2 * bi + 0], pv.x, wd);
                    ffma2(acc2[2 * bi + 1], pv.y, wd);
                }
            }
#pragma unroll
            for (int u = 0; u < 4; u++) wreg[u] = wnext[u];
        }
    }
#pragma unroll
    for (int p = 0; p < 32; p++) {
        float lo, hi;
        unpack2(acc2[p], lo, hi);
        W2[((size_t)(2 * p + 0) * Dsz + k) * Dsz + e] = lo;
        W2[((size_t)(2 * p + 1) * Dsz + k) * Dsz + e] = hi;
    }
}

// ---------------- GRU chain: 2 batches per block, FFMA2 over batch pairs ----------------
__global__ void gru_kernel(const float* __restrict__ gi, const float* __restrict__ WhhT,
                           const float* __restrict__ bhh, const float* __restrict__ query,
                           float* __restrict__ sib, int T)
{
    __shared__ float hT[256][2];   // [d][batch]
    __shared__ float ghs[768][2];  // [o][batch]
    const int bb0 = blockIdx.x * 2;
    const int o = threadIdx.x;   // 0..767

    if (o < 256) {
        float qv = query[o];
        hT[o][0] = qv;
        hT[o][1] = qv;
        sib[((size_t)0 * Bsz + bb0 + 0) * Dsz + o] = qv;
        sib[((size_t)0 * Bsz + bb0 + 1) * Dsz + o] = qv;
    }
    __syncthreads();
    const float bo = bhh[o];

    for (int t = 0; t < T - 1; t++) {
        ull acc = 0ull;
        const float* wcol = WhhT + o;
#pragma unroll 8
        for (int d = 0; d < 256; d++) {
            float w = wcol[d * 768];
            ull h2 = *reinterpret_cast<const ull*>(&hT[d][0]);
            ffma2(acc, h2, dup2(w));
        }
        float g0, g1;
        unpack2(acc, g0, g1);
        ghs[o][0] = g0 + bo;
        ghs[o][1] = g1 + bo;
        __syncthreads();
        if (o < 256) {
#pragma unroll
            for (int j = 0; j < 2; j++) {
                const float* gib = gi + ((size_t)t * Bsz + bb0 + j) * 768;
                float r = fast_sigmoid(gib[o] + ghs[o][j]);
                float z = fast_sigmoid(gib[256 + o] + ghs[256 + o][j]);
                float n = fast_tanh_exact(gib[512 + o] + r * ghs[512 + o][j]);
                float hn = (1.f - z) * n + z * hT[o][j];
                hT[o][j] = hn;
                sib[((size_t)(t + 1) * Bsz + bb0 + j) * Dsz + o] = hn;
            }
        }
        __syncthreads();
    }
}

// ---------------- q[t][b][k] = sum_e W2[b][k][e]*sib[t][b][e] + bil_b[k] ----------------
template<int T>
__global__ void q_kernel(const float* __restrict__ W2, const float* __restrict__ sib,
                         const float* __restrict__ bil_b, float* __restrict__ q)
{
    __shared__ float ssib[T][256];
    const int b = blockIdx.x;
    for (int i = threadIdx.x; i < T * 256; i += 256) {
        int t = i >> 8;
        int e = i & 255;
        ssib[t][e] = sib[((size_t)t * Bsz + b) * Dsz + e];
    }
    __syncthreads();
    const int k = threadIdx.x;
    float acc[T];
#pragma unroll
    for (int t = 0; t < T; t++) acc[t] = 0.f;
    const float* wrow = W2 + ((size_t)b * Dsz + k) * Dsz;
#pragma unroll 1
    for (int e0 = 0; e0 < 256; e0 += 8) {
        float4 w0 = *reinterpret_cast<const float4*>(wrow + e0);
        float4 w1 = *reinterpret_cast<const float4*>(wrow + e0 + 4);
#pragma unroll
        for (int t = 0; t < T; t++) {
            const float4* sb = reinterpret_cast<const float4*>(&ssib[t][e0]);
            float4 s0 = sb[0], s1 = sb[1];
            acc[t] += w0.x * s0.x + w0.y * s0.y + w0.z * s0.z + w0.w * s0.w
                    + w1.x * s1.x + w1.y * s1.y + w1.z * s1.z + w1.w * s1.w;
        }
    }
    float bb = bil_b[k];
#pragma unroll
    for (int t = 0; t < T; t++)
        q[((size_t)t * Bsz + b) * Dsz + k] = acc[t] + bb;
}

// ---------------- scores[b][t][l] = sum_d v[d]*tanh(projkT[b][d][l] + qq[t][b][d]) -----
template<int T>
__global__ void score_kernel(const float* __restrict__ projkT, const float* __restrict__ qq,
                             const float* __restrict__ attn_v, float* __restrict__ scores)
{
    __shared__ float sqq[T][256];
    __shared__ float sv[256];
    const int b = blockIdx.y;
    const int l = blockIdx.x * 256 + threadIdx.x;
    for (int i = threadIdx.x; i < T * 256; i += 256) {
        int t = i >> 8;
        int d = i & 255;
        sqq[t][d] = qq[((size_t)t * Bsz + b) * Dsz + d];
    }
    sv[threadIdx.x] = attn_v[threadIdx.x];
    __syncthreads();

    float acc[T];
#pragma unroll
    for (int t = 0; t < T; t++) acc[t] = 0.f;
    const float* pk = projkT + (size_t)b * Dsz * Lsz + l;
#pragma unroll 2
    for (int d = 0; d < 256; d++) {
        float p = pk[(size_t)d * Lsz];
        float v = sv[d];
#pragma unroll
        for (int t = 0; t < T; t++)
            acc[t] += v * tanha(p + sqq[t][d]);
    }
#pragma unroll
    for (int t = 0; t < T; t++)
        scores[((size_t)b * T + t) * Lsz + l] = acc[t];
}

// ---------------- softmax-at-gold: out[b][t] = softmax(scores[b][t])[gold[b][t]] -------
__global__ void prob_kernel(const float* __restrict__ scores, const int* __restrict__ mask,
                            const int* __restrict__ gold, int T, float* __restrict__ out)
{
    __shared__ float red[256];
    const int bt = blockIdx.x;
    const int b = bt / T;
    const int t = bt - b * T;
    const float* s = scores + (size_t)bt * Lsz;
    const int* mk = mask + (size_t)b * Lsz;

    float vals[8];
    float mx = -3.0e38f;
#pragma unroll
    for (int j = 0; j < 8; j++) {
        int l = threadIdx.x + j * 256;
        float v = (mk[l] != 0) ? s[l] : -1e9f;
        vals[j] = v;
        mx = fmaxf(mx, v);
    }
    red[threadIdx.x] = mx;
    __syncthreads();
    for (int st = 128; st > 0; st >>= 1) {
        if (threadIdx.x < st) red[threadIdx.x] = fmaxf(red[threadIdx.x], red[threadIdx.x + st]);
        __syncthreads();
    }
    float M = red[0];
    __syncthreads();
    float sm = 0.f;
#pragma unroll
    for (int j = 0; j < 8; j++) sm += __expf(vals[j] - M);
    red[threadIdx.x] = sm;
    __syncthreads();
    for (int st = 128; st > 0; st >>= 1) {
        if (threadIdx.x < st) red[threadIdx.x] += red[threadIdx.x + st];
        __syncthreads();
    }
    if (threadIdx.x == 0) {
        int g = gold[b * T + t];
        float sg = (mk[g] != 0) ? s[g] : -1e9f;
        out[b * T + t] = __expf(sg - M) / red[0];
    }
}

// ---------------- host orchestration ----------------
static void run_network(const float* feat, const float* query, const int* gold, const int* mask,
                        const float* bilW, const float* bil_b, const float* Wq, const float* Wk,
                        const float* attn_b, const float* attn_v, const float* Wih,
                        const float* Whh, const float* bih, const float* bhh,
                        int T, float* out,
                        float* s_projkT, float* s_W2, float* s_sib, float* s_gi,
                        float* s_q, float* s_qq, float* s_scores, float* s_WhhT)
{
    const int M = T * Bsz;
    transpose_whh<<<768, 256>>>(Whh, s_WhhT);
    // gi = gather(feat, gold) @ Wih^T + bih   (M x 768)
    tgemm_kernel<1, 0, 1, 1><<<dim3(M / BM, 768 / BN), 256>>>(
        feat, Dsz, Wih, bih, s_gi, 768, M, 768, Dsz, gold, T, Lsz);
    gru_kernel<<<32, 768>>>(s_gi, s_WhhT, bhh, query, s_sib, T);
    w2_kernel<<<256, 256>>>(bilW, feat, s_W2);
    if (T == TC) q_kernel<TC><<<Bsz, 256>>>(s_W2, s_sib, bil_b, s_q);
    else         q_kernel<TP><<<Bsz, 256>>>(s_W2, s_sib, bil_b, s_q);
    // qq = q @ Wq + attn_b   (M x 256)
    tgemm_kernel<0, 0, 0, 1><<<dim3(M / BM, Dsz / BN), 256>>>(
        s_q, Dsz, Wq, attn_b, s_qq, Dsz, M, Dsz, Dsz, nullptr, 0, 0);
    // projkT[b][d][l] = (emb_b @ Wk)^T   per-b via grid.z
    tgemm_kernel<0, 1, 0, 0><<<dim3(Lsz / BM, Dsz / BN, Bsz), 256>>>(
        feat, Dsz, Wk, nullptr, s_projkT, Lsz, Lsz, Dsz, Dsz, nullptr, 0, 0);
    if (T == TC) score_kernel<TC><<<dim3(Lsz / 256, Bsz), 256>>>(s_projkT, s_qq, attn_v, s_scores);
    else         score_kernel<TP><<<dim3(Lsz / 256, Bsz), 256>>>(s_projkT, s_qq, attn_v, s_scores);
    prob_kernel<<<Bsz * T, 256>>>(s_scores, mask, gold, T, out);
}

extern "C" void kernel_launch(void* const* d_in, const int* in_sizes, int n_in,
                              void* d_out, int out_size)
{
    (void)n_in; (void)out_size;
    int iFeat, iMask, iGC, iGP, iQC, iQP, c0, p0;
    if (in_sizes[1] == Bsz * Lsz) {
        iFeat = 0; iMask = 1; iGC = 2; iGP = 3; iQC = 4; iQP = 5; c0 = 6; p0 = 16;
    } else {
        iFeat = 0; iQC = 1; iQP = 2; c0 = 3; p0 = 13; iMask = 23; iGC = 24; iGP = 25;
    }
    const float* feat = (const float*)d_in[iFeat];
    const int* mask = (const int*)d_in[iMask];
    const int* gold_c = (const int*)d_in[iGC];
    const int* gold_p = (const int*)d_in[iGP];
    const float* q_c = (const float*)d_in[iQC];
    const float* q_p = (const float*)d_in[iQP];
    float* out = (float*)d_out;

    float *s_projkT, *s_W2, *s_sib, *s_gi, *s_q, *s_qq, *s_scores, *s_WhhT;
    cudaGetSymbolAddress((void**)&s_projkT, g_projkT);
    cudaGetSymbolAddress((void**)&s_W2, g_W2);
    cudaGetSymbolAddress((void**)&s_sib, g_sib);
    cudaGetSymbolAddress((void**)&s_gi, g_gi);
    cudaGetSymbolAddress((void**)&s_q, g_q);
    cudaGetSymbolAddress((void**)&s_qq, g_qq);
    cudaGetSymbolAddress((void**)&s_scores, g_scores);
    cudaGetSymbolAddress((void**)&s_WhhT, g_WhhT);

    run_network(feat, q_c, gold_c, mask,
                (const float*)d_in[c0 + 0], (const float*)d_in[c0 + 1],
                (const float*)d_in[c0 + 2], (const float*)d_in[c0 + 3],
                (const float*)d_in[c0 + 4], (const float*)d_in[c0 + 5],
                (const float*)d_in[c0 + 6], (const float*)d_in[c0 + 7],
                (const float*)d_in[c0 + 8], (const float*)d_in[c0 + 9],
                TC, out,
                s_projkT, s_W2, s_sib, s_gi, s_q, s_qq, s_scores, s_WhhT);

    run_network(feat, q_p, gold_p, mask,
                (const float*)d_in[p0 + 0], (const float*)d_in[p0 + 1],
                (const float*)d_in[p0 + 2], (const float*)d_in[p0 + 3],
                (const float*)d_in[p0 + 4], (const float*)d_in[p0 + 5],
                (const float*)d_in[p0 + 6], (const float*)d_in[p0 + 7],
                (const float*)d_in[p0 + 8], (const float*)d_in[p0 + 9],
                TP, out + Bsz * TC,
                s_projkT, s_W2, s_sib, s_gi, s_q, s_qq, s_scores, s_WhhT);
}